// round 8
// baseline (speedup 1.0000x reference)
#include <cuda_runtime.h>
#include <cstdint>

// Problem constants (re-derived from in_sizes where possible).
#define D        64
#define ITERS    4
#define OUTC     ((ITERS + 1) * D)   // 320 output columns
#define N_MAX    50000
#define E_MAX    800000
#define TPB      256

// -------- scratch (no allocation allowed; __device__ globals) --------
__device__ float g_sum[N_MAX * D];   // per-node accumulator, 12.8 MB
__device__ float g_deg[N_MAX];       // in-degree (float count)
__device__ float g_invdeg[N_MAX];    // 1 / max(deg, 1)
__device__ int   g_src[E_MAX];       // normalized int32 indices
__device__ int   g_dst[E_MAX];
__device__ int   g_is64;             // 1 if edge_index buffer is int64

// ---------------- kernels ----------------

// Detect int64-vs-int32 edge_index layout. Reads only the first 2*n_check
// int32 words, which is in-bounds for EITHER dtype (buffer holds >= 1.6M
// int32 words minimum). If the data is little-endian int64 with values
// < 2^31, every odd word is the zero high-half.
__global__ void detect_kernel(const int* __restrict__ p32, int n_check) {
    __shared__ int zc;
    if (threadIdx.x == 0) zc = 0;
    __syncthreads();
    int cnt = 0;
    for (int i = threadIdx.x; i < n_check; i += blockDim.x)
        if (p32[2 * i + 1] == 0) cnt++;
    atomicAdd(&zc, cnt);
    __syncthreads();
    if (threadIdx.x == 0) g_is64 = (zc > (n_check * 9) / 10) ? 1 : 0;
}

// Zero deg + sum each launch (determinism across graph replays).
__global__ void zero_kernel(int n_nodes) {
    int stride = gridDim.x * blockDim.x;
    int t = blockIdx.x * blockDim.x + threadIdx.x;
    for (int i = t; i < n_nodes; i += stride) g_deg[i] = 0.0f;
    int total4 = n_nodes * (D / 4);
    float4* s4 = reinterpret_cast<float4*>(g_sum);
    for (int i = t; i < total4; i += stride) s4[i] = make_float4(0.f, 0.f, 0.f, 0.f);
}

// Normalize indices into int32 arrays + accumulate in-degree (fused).
__global__ void convert_deg_kernel(const int* __restrict__ p32, int n_edges) {
    int e = blockIdx.x * blockDim.x + threadIdx.x;
    if (e >= n_edges) return;
    int s, d;
    if (g_is64) {                      // int64: low word of each 8-byte value
        s = p32[2 * e];
        d = p32[2 * ((size_t)n_edges + e)];
    } else {                           // int32: contiguous [2, E]
        s = p32[e];
        d = p32[n_edges + e];
    }
    g_src[e] = s;
    g_dst[e] = d;
    atomicAdd(&g_deg[d], 1.0f);
}

__global__ void invdeg_kernel(int n_nodes) {
    int i = blockIdx.x * blockDim.x + threadIdx.x;
    if (i < n_nodes) g_invdeg[i] = 1.0f / fmaxf(g_deg[i], 1.0f);
}

// Copy x into output columns [0, 64). 16 threads per node, float4 each.
__global__ void copy_kernel(const float* __restrict__ x, float* __restrict__ out,
                            int n_nodes) {
    int t = blockIdx.x * blockDim.x + threadIdx.x;
    int i = t >> 4;
    int lane = t & 15;
    if (i >= n_nodes) return;
    float4 v = reinterpret_cast<const float4*>(x + (size_t)i * D)[lane];
    reinterpret_cast<float4*>(out + (size_t)i * OUTC)[lane] = v;
}

// Vector reduction into global memory: one 16B RED per thread.
__device__ __forceinline__ void red_add_f32x4(float* addr, float4 v) {
    asm volatile("red.global.add.v4.f32 [%0], {%1, %2, %3, %4};"
                 :: "l"(addr), "f"(v.x), "f"(v.y), "f"(v.z), "f"(v.w)
                 : "memory");
}

// Gather x[src] from the previous iteration's output slab and scatter-add
// into g_sum[dst]. 16 threads per edge, float4 per thread (covers D=64).
__global__ void scatter_kernel(const float* __restrict__ xin,  // = out + (k-1)*D
                               int n_edges) {
    int t = blockIdx.x * blockDim.x + threadIdx.x;
    int e = t >> 4;
    int lane = t & 15;
    if (e >= n_edges) return;
    int s = g_src[e];
    int d = g_dst[e];
    float4 v = reinterpret_cast<const float4*>(xin + (size_t)s * OUTC)[lane];
    red_add_f32x4(reinterpret_cast<float*>(
                      reinterpret_cast<float4*>(g_sum + (size_t)d * D) + lane),
                  v);
}

// x_k = 0.5 * (x_{k-1} + sum * invdeg); also resets g_sum for the next iter.
__global__ void combine_kernel(float* __restrict__ out, int n_nodes, int k) {
    int t = blockIdx.x * blockDim.x + threadIdx.x;
    int i = t >> 4;
    int lane = t & 15;
    if (i >= n_nodes) return;
    float4* sp = reinterpret_cast<float4*>(g_sum + (size_t)i * D) + lane;
    float4 s = *sp;
    float inv = g_invdeg[i];
    float4 x = reinterpret_cast<const float4*>(
                   out + (size_t)i * OUTC + (size_t)(k - 1) * D)[lane];
    float4 r;
    r.x = 0.5f * fmaf(s.x, inv, x.x);
    r.y = 0.5f * fmaf(s.y, inv, x.y);
    r.z = 0.5f * fmaf(s.z, inv, x.z);
    r.w = 0.5f * fmaf(s.w, inv, x.w);
    reinterpret_cast<float4*>(out + (size_t)i * OUTC + (size_t)k * D)[lane] = r;
    *sp = make_float4(0.f, 0.f, 0.f, 0.f);  // reset for next iteration
}

// ---------------- launch ----------------

extern "C" void kernel_launch(void* const* d_in, const int* in_sizes, int n_in,
                              void* d_out, int out_size) {
    const float* x   = (const float*)d_in[0];
    const int*   p32 = (const int*)d_in[1];   // raw edge_index words (int32 view)
    float*       out = (float*)d_out;

    const int n_nodes = in_sizes[0] / D;      // 50000
    const int n_edges = in_sizes[1] / 2;      // 800000

    // 1. zero scratch + detect index dtype
    zero_kernel<<<512, TPB>>>(n_nodes);
    detect_kernel<<<1, TPB>>>(p32, 2048);

    // 2. normalize indices + degree + reciprocal
    convert_deg_kernel<<<(n_edges + TPB - 1) / TPB, TPB>>>(p32, n_edges);
    invdeg_kernel<<<(n_nodes + TPB - 1) / TPB, TPB>>>(n_nodes);

    // 3. iteration 0 features = x
    {
        int threads = n_nodes * 16;
        copy_kernel<<<(threads + TPB - 1) / TPB, TPB>>>(x, out, n_nodes);
    }

    // 4. WL iterations
    for (int k = 1; k <= ITERS; k++) {
        {
            long long threads = (long long)n_edges * 16;
            int blocks = (int)((threads + TPB - 1) / TPB);
            scatter_kernel<<<blocks, TPB>>>(out + (size_t)(k - 1) * D, n_edges);
        }
        {
            int threads = n_nodes * 16;
            combine_kernel<<<(threads + TPB - 1) / TPB, TPB>>>(out, n_nodes, k);
        }
    }
}

// round 9
// speedup vs baseline: 1.9512x; 1.9512x over previous
#include <cuda_runtime.h>
#include <cstdint>

#define D        64
#define ITERS    4
#define OUTC     ((ITERS + 1) * D)   // 320 output columns
#define N_MAX    50016               // padded
#define E_MAX    800000
#define TPB      256
#define SCAN_B   256

// -------- scratch (__device__ globals; no allocation allowed) --------
__device__ int g_deg[N_MAX];         // in-degree (int)
__device__ int g_rowptr[N_MAX + 1];  // CSR row pointers (by dst)
__device__ int g_cursor[N_MAX];      // placement cursors
__device__ int g_blocksum[SCAN_B];   // scan partials (<=256 blocks)
__device__ int g_blockoff[SCAN_B];
__device__ int g_src[E_MAX];         // normalized int32 indices
__device__ int g_dst[E_MAX];
__device__ int g_col[E_MAX];         // CSR column (src ids grouped by dst)
__device__ int g_is64;               // 1 if edge_index buffer is int64

// ---------------- kernels ----------------

// Detect int64-vs-int32 edge_index layout (reads a prefix valid for either).
__global__ void detect_kernel(const int* __restrict__ p32, int n_check) {
    __shared__ int zc;
    if (threadIdx.x == 0) zc = 0;
    __syncthreads();
    int cnt = 0;
    for (int i = threadIdx.x; i < n_check; i += blockDim.x)
        if (p32[2 * i + 1] == 0) cnt++;
    atomicAdd(&zc, cnt);
    __syncthreads();
    if (threadIdx.x == 0) g_is64 = (zc > (n_check * 9) / 10) ? 1 : 0;
}

__global__ void zero_deg_kernel(int n_nodes) {
    int i = blockIdx.x * blockDim.x + threadIdx.x;
    if (i < n_nodes) g_deg[i] = 0;
}

// Normalize indices to int32 + in-degree histogram (fused).
__global__ void convert_deg_kernel(const int* __restrict__ p32, int n_edges) {
    int e = blockIdx.x * blockDim.x + threadIdx.x;
    if (e >= n_edges) return;
    int s, d;
    if (g_is64) {
        s = p32[2 * e];
        d = p32[2 * ((size_t)n_edges + e)];
    } else {
        s = p32[e];
        d = p32[n_edges + e];
    }
    g_src[e] = s;
    g_dst[e] = d;
    atomicAdd(&g_deg[d], 1);
}

// --- 3-kernel exclusive scan of g_deg -> g_rowptr ---
__global__ void scan1_kernel(int n_nodes) {
    __shared__ int sm[SCAN_B];
    int i = blockIdx.x * SCAN_B + threadIdx.x;
    int v = (i < n_nodes) ? g_deg[i] : 0;
    sm[threadIdx.x] = v;
    __syncthreads();
    for (int off = 1; off < SCAN_B; off <<= 1) {
        int t = (threadIdx.x >= off) ? sm[threadIdx.x - off] : 0;
        __syncthreads();
        sm[threadIdx.x] += t;
        __syncthreads();
    }
    if (i < n_nodes) g_rowptr[i] = sm[threadIdx.x] - v;   // exclusive
    if (threadIdx.x == SCAN_B - 1) g_blocksum[blockIdx.x] = sm[threadIdx.x];
}

__global__ void scan2_kernel(int nblocks) {   // <<<1, SCAN_B>>>
    __shared__ int sm[SCAN_B];
    int v = (threadIdx.x < nblocks) ? g_blocksum[threadIdx.x] : 0;
    sm[threadIdx.x] = v;
    __syncthreads();
    for (int off = 1; off < SCAN_B; off <<= 1) {
        int t = (threadIdx.x >= off) ? sm[threadIdx.x - off] : 0;
        __syncthreads();
        sm[threadIdx.x] += t;
        __syncthreads();
    }
    g_blockoff[threadIdx.x] = sm[threadIdx.x] - v;        // exclusive
}

__global__ void scan3_kernel(int n_nodes, int n_edges) {
    int i = blockIdx.x * blockDim.x + threadIdx.x;
    if (i < n_nodes) {
        int r = g_rowptr[i] + g_blockoff[i / SCAN_B];
        g_rowptr[i] = r;
        g_cursor[i] = r;
    }
    if (i == n_nodes) g_rowptr[n_nodes] = n_edges;
}

// Place src ids into CSR order (by dst).
__global__ void place_kernel(int n_edges) {
    int e = blockIdx.x * blockDim.x + threadIdx.x;
    if (e >= n_edges) return;
    int d = g_dst[e];
    int pos = atomicAdd(&g_cursor[d], 1);
    g_col[pos] = g_src[e];
}

// Copy x into output columns [0, 64). 16 threads per node, float4 each.
__global__ void copy_kernel(const float* __restrict__ x, float* __restrict__ out,
                            int n_nodes) {
    int t = blockIdx.x * blockDim.x + threadIdx.x;
    int i = t >> 4;
    int lane = t & 15;
    if (i >= n_nodes) return;
    float4 v = reinterpret_cast<const float4*>(x + (size_t)i * D)[lane];
    reinterpret_cast<float4*>(out + (size_t)i * OUTC)[lane] = v;
}

// Fused pull + combine:
//   out_k[i] = 0.5 * ( out_{k-1}[i] + (1/max(deg,1)) * sum_j out_{k-1}[col[j]] )
// 16 threads per node, float4 per thread; neighbor sum in registers.
__global__ void pull_kernel(const float* __restrict__ xin,   // = out + (k-1)*D
                            float* __restrict__ xout,        // = out + k*D
                            int n_nodes) {
    int t = blockIdx.x * blockDim.x + threadIdx.x;
    int i = t >> 4;
    int lane = t & 15;
    if (i >= n_nodes) return;
    int start = g_rowptr[i];
    int end   = g_rowptr[i + 1];
    float4 acc = make_float4(0.f, 0.f, 0.f, 0.f);
#pragma unroll 4
    for (int j = start; j < end; j++) {
        int s = __ldg(&g_col[j]);
        float4 v = reinterpret_cast<const float4*>(xin + (size_t)s * OUTC)[lane];
        acc.x += v.x; acc.y += v.y; acc.z += v.z; acc.w += v.w;
    }
    int deg = end - start;
    float inv = 1.0f / (float)(deg > 0 ? deg : 1);
    float4 xv = reinterpret_cast<const float4*>(xin + (size_t)i * OUTC)[lane];
    float4 r;
    r.x = 0.5f * fmaf(acc.x, inv, xv.x);
    r.y = 0.5f * fmaf(acc.y, inv, xv.y);
    r.z = 0.5f * fmaf(acc.z, inv, xv.z);
    r.w = 0.5f * fmaf(acc.w, inv, xv.w);
    reinterpret_cast<float4*>(xout + (size_t)i * OUTC)[lane] = r;
}

// ---------------- launch ----------------

extern "C" void kernel_launch(void* const* d_in, const int* in_sizes, int n_in,
                              void* d_out, int out_size) {
    const float* x   = (const float*)d_in[0];
    const int*   p32 = (const int*)d_in[1];
    float*       out = (float*)d_out;

    const int n_nodes = in_sizes[0] / D;      // 50000
    const int n_edges = in_sizes[1] / 2;      // 800000

    const int nb_nodes  = (n_nodes + TPB - 1) / TPB;          // 196
    const int nb_edges  = (n_edges + TPB - 1) / TPB;          // 3125
    const int nb_scan   = (n_nodes + SCAN_B - 1) / SCAN_B;    // 196
    const int nb_nodes1 = (n_nodes + 1 + TPB - 1) / TPB;

    // 1. dtype detect + degree histogram
    zero_deg_kernel<<<nb_nodes, TPB>>>(n_nodes);
    detect_kernel<<<1, TPB>>>(p32, 2048);
    convert_deg_kernel<<<nb_edges, TPB>>>(p32, n_edges);

    // 2. CSR build: exclusive scan + placement
    scan1_kernel<<<nb_scan, SCAN_B>>>(n_nodes);
    scan2_kernel<<<1, SCAN_B>>>(nb_scan);
    scan3_kernel<<<nb_nodes1, TPB>>>(n_nodes, n_edges);
    place_kernel<<<nb_edges, TPB>>>(n_edges);

    // 3. iteration 0 features = x
    {
        int threads = n_nodes * 16;
        copy_kernel<<<(threads + TPB - 1) / TPB, TPB>>>(x, out, n_nodes);
    }

    // 4. WL iterations: fused pull + combine
    for (int k = 1; k <= ITERS; k++) {
        int threads = n_nodes * 16;
        pull_kernel<<<(threads + TPB - 1) / TPB, TPB>>>(
            out + (size_t)(k - 1) * D, out + (size_t)k * D, n_nodes);
    }
}